// round 4
// baseline (speedup 1.0000x reference)
#include <cuda_runtime.h>
#include <cuda_bf16.h>
#include <math.h>

// Problem constants
#define BATCH 2
#define SEQ   2048
#define DMODEL 4096
#define NH    32          // query heads
#define NKV   8           // kv heads
#define HD    128         // head dim
#define GQA   4           // NH / NKV
#define QKVN  6144        // (NH + 2*NKV) * HD
#define MROWS 4096        // BATCH * SEQ

// Scratch: device globals (no allocation allowed)
__device__ float g_qkv[(size_t)MROWS * QKVN];    // ~100.7 MB
__device__ float g_attn[(size_t)MROWS * DMODEL]; // ~67 MB

// ---------------------------------------------------------------------------
// GEMM: C[M,N] = A[M,K] @ B[K,N], row-major, all dims multiples of tile sizes.
// 128x128 block tile, BK=16, 256 threads, 8x8 micro-tile, register prefetch.
// ---------------------------------------------------------------------------
__global__ __launch_bounds__(256) void gemm_kernel(
    const float* __restrict__ A, const float* __restrict__ B,
    float* __restrict__ C, int M, int N, int K)
{
    __shared__ float As[16][128];  // transposed: As[k][m]
    __shared__ float Bs[16][128];

    const int tid = threadIdx.x;
    const int bm = blockIdx.y * 128;
    const int bn = blockIdx.x * 128;
    const int tm = tid >> 4;   // 0..15 -> 8 rows each
    const int tn = tid & 15;   // 0..15 -> 8 cols each

    const float* Ab = A + (size_t)bm * K;
    const float* Bb = B + bn;

    float acc[8][8];
#pragma unroll
    for (int i = 0; i < 8; i++)
#pragma unroll
        for (int j = 0; j < 8; j++) acc[i][j] = 0.0f;

    float4 pa[2], pb[2];
    // initial prefetch (k0 = 0)
#pragma unroll
    for (int i = 0; i < 2; i++) {
        int idx = i * 256 + tid;
        int ra = idx >> 2, ca = idx & 3;               // A: 128 rows x 4 float4
        pa[i] = *(const float4*)(Ab + (size_t)ra * K + ca * 4);
        int rb = idx >> 5, cb = idx & 31;              // B: 16 rows x 32 float4
        pb[i] = *(const float4*)(Bb + (size_t)rb * N + cb * 4);
    }

    for (int k0 = 0; k0 < K; k0 += 16) {
        // store prefetched tile to smem
#pragma unroll
        for (int i = 0; i < 2; i++) {
            int idx = i * 256 + tid;
            int ra = idx >> 2, ca = idx & 3;
            As[ca * 4 + 0][ra] = pa[i].x;
            As[ca * 4 + 1][ra] = pa[i].y;
            As[ca * 4 + 2][ra] = pa[i].z;
            As[ca * 4 + 3][ra] = pa[i].w;
            int rb = idx >> 5, cb = idx & 31;
            *(float4*)&Bs[rb][cb * 4] = pb[i];
        }
        __syncthreads();

        // prefetch next tile (overlaps with compute)
        if (k0 + 16 < K) {
#pragma unroll
            for (int i = 0; i < 2; i++) {
                int idx = i * 256 + tid;
                int ra = idx >> 2, ca = idx & 3;
                pa[i] = *(const float4*)(Ab + (size_t)ra * K + (k0 + 16) + ca * 4);
                int rb = idx >> 5, cb = idx & 31;
                pb[i] = *(const float4*)(Bb + (size_t)(k0 + 16 + rb) * N + cb * 4);
            }
        }

#pragma unroll
        for (int kk = 0; kk < 16; kk++) {
            float a[8], b[8];
            *(float4*)&a[0] = *(const float4*)&As[kk][tm * 8];
            *(float4*)&a[4] = *(const float4*)&As[kk][tm * 8 + 4];
            *(float4*)&b[0] = *(const float4*)&Bs[kk][tn * 8];
            *(float4*)&b[4] = *(const float4*)&Bs[kk][tn * 8 + 4];
#pragma unroll
            for (int i = 0; i < 8; i++)
#pragma unroll
                for (int j = 0; j < 8; j++)
                    acc[i][j] += a[i] * b[j];
        }
        __syncthreads();
    }

#pragma unroll
    for (int i = 0; i < 8; i++) {
        float* cp = C + (size_t)(bm + tm * 8 + i) * N + bn + tn * 8;
        *(float4*)cp       = make_float4(acc[i][0], acc[i][1], acc[i][2], acc[i][3]);
        *(float4*)(cp + 4) = make_float4(acc[i][4], acc[i][5], acc[i][6], acc[i][7]);
    }
}

// ---------------------------------------------------------------------------
// Fused per-head RMSNorm + NeoX RoPE over q (heads 0..31) and k (heads 32..39)
// in-place in g_qkv. One warp per (row, head). Heads 0..39 are contiguous
// (q block then k block), offset = head*128. V untouched.
// ---------------------------------------------------------------------------
__global__ __launch_bounds__(256) void normrope_kernel(
    float* __restrict__ qkv, const int* __restrict__ positions,
    const float* __restrict__ qw, const float* __restrict__ kw)
{
    int gw = (blockIdx.x * blockDim.x + threadIdx.x) >> 5;
    int lane = threadIdx.x & 31;
    int row = gw / 40;
    int head = gw - row * 40;
    if (row >= MROWS) return;

    const float* w = (head < 32) ? qw : kw;
    float* ptr = qkv + (size_t)row * QKVN + head * HD;

    // lane owns d in {lane, lane+32, lane+64, lane+96}
    float x0 = ptr[lane];
    float x1 = ptr[lane + 32];
    float x2 = ptr[lane + 64];
    float x3 = ptr[lane + 96];

    float ss = x0 * x0 + x1 * x1 + x2 * x2 + x3 * x3;
#pragma unroll
    for (int off = 1; off < 32; off <<= 1)
        ss += __shfl_xor_sync(0xffffffffu, ss, off);

    float r = rsqrtf(ss * (1.0f / 128.0f) + 1e-6f);
    x0 = x0 * r * w[lane];
    x1 = x1 * r * w[lane + 32];
    x2 = x2 * r * w[lane + 64];
    x3 = x3 * r * w[lane + 96];

    // RoPE (NeoX halves): pairs (lane, lane+64) with freq idx lane,
    //                     (lane+32, lane+96) with freq idx lane+32
    float pf = (float)positions[row];
    float inv0 = powf(10000.0f, -((float)(2 * lane)) / 128.0f);
    float inv1 = powf(10000.0f, -((float)(2 * (lane + 32))) / 128.0f);
    float s0, c0, s1, c1;
    sincosf(pf * inv0, &s0, &c0);
    sincosf(pf * inv1, &s1, &c1);

    float y0 = x0 * c0 - x2 * s0;
    float y2 = x2 * c0 + x0 * s0;
    float y1 = x1 * c1 - x3 * s1;
    float y3 = x3 * c1 + x1 * s1;

    ptr[lane]      = y0;
    ptr[lane + 32] = y1;
    ptr[lane + 64] = y2;
    ptr[lane + 96] = y3;
}

// ---------------------------------------------------------------------------
// Causal GQA flash attention, fp32. Grid (S/64, NH, BATCH), 256 threads.
// Q tile 64x128, iterate K/V tiles of 64 with online softmax.
// smem: QS[64][132], KS[128][65] (transposed), VS[64][132], PS[64][65],
//       row stats m/l/scale. 118 KB dynamic smem -> 1 CTA/SM.
// ---------------------------------------------------------------------------
__global__ __launch_bounds__(256) void attn_kernel(
    const float* __restrict__ qkv, float* __restrict__ attn_out)
{
    extern __shared__ float sm[];
    float* QS  = sm;                 // 64*132 = 8448
    float* KS  = QS + 64 * 132;      // 128*65 = 8320
    float* VS  = KS + 128 * 65;      // 64*132 = 8448
    float* PS  = VS + 64 * 132;      // 64*65  = 4160
    float* RM  = PS + 64 * 65;       // 64
    float* RL  = RM + 64;            // 64
    float* RSC = RL + 64;            // 64

    const int tid = threadIdx.x;
    const int qb = blockIdx.x;
    const int h  = blockIdx.y;
    const int b  = blockIdx.z;
    const int kh = h >> 2;  // GQA = 4

    const float* qbase = qkv + (size_t)(b * SEQ + qb * 64) * QKVN + h * HD;
    const float* kbase = qkv + (size_t)(b * SEQ) * QKVN + NH * HD + kh * HD;
    const float* vbase = qkv + (size_t)(b * SEQ) * QKVN + (NH + NKV) * HD + kh * HD;

    // load Q tile (64 x 128)
#pragma unroll
    for (int i = 0; i < 8; i++) {
        int idx = i * 256 + tid;
        int rr = idx >> 5, c4 = idx & 31;
        float4 v = *(const float4*)(qbase + (size_t)rr * QKVN + c4 * 4);
        *(float4*)&QS[rr * 132 + c4 * 4] = v;
    }
    if (tid < 64) { RM[tid] = -1e30f; RL[tid] = 0.0f; }

    const int wid = tid >> 5, lane = tid & 31;   // O-phase mapping
    const int ty  = tid >> 4, tx   = tid & 15;   // S-phase mapping

    float o[8][4];
#pragma unroll
    for (int i = 0; i < 8; i++)
#pragma unroll
        for (int j = 0; j < 4; j++) o[i][j] = 0.0f;

    __syncthreads();

    for (int kb = 0; kb <= qb; kb++) {
        // load K (transposed) and V tiles
#pragma unroll
        for (int i = 0; i < 8; i++) {
            int idx = i * 256 + tid;
            int n = idx >> 5, c4 = idx & 31;
            const float* kr = kbase + (size_t)(kb * 64 + n) * QKVN + c4 * 4;
            float4 kv = *(const float4*)kr;
            KS[(c4 * 4 + 0) * 65 + n] = kv.x;
            KS[(c4 * 4 + 1) * 65 + n] = kv.y;
            KS[(c4 * 4 + 2) * 65 + n] = kv.z;
            KS[(c4 * 4 + 3) * 65 + n] = kv.w;
            const float* vr = vbase + (size_t)(kb * 64 + n) * QKVN + c4 * 4;
            *(float4*)&VS[n * 132 + c4 * 4] = *(const float4*)vr;
        }
        __syncthreads();

        // S = Q @ K^T  (each thread: 4 rows x 4 cols)
        float s[4][4];
#pragma unroll
        for (int i = 0; i < 4; i++)
#pragma unroll
            for (int j = 0; j < 4; j++) s[i][j] = 0.0f;

#pragma unroll 4
        for (int d = 0; d < 128; d++) {
            float qv[4], kv[4];
#pragma unroll
            for (int i = 0; i < 4; i++) qv[i] = QS[(ty * 4 + i) * 132 + d];
#pragma unroll
            for (int j = 0; j < 4; j++) kv[j] = KS[d * 65 + tx * 4 + j];
#pragma unroll
            for (int i = 0; i < 4; i++)
#pragma unroll
                for (int j = 0; j < 4; j++)
                    s[i][j] += qv[i] * kv[j];
        }

        const float sc = 0.08838834764831845f;  // HD^-0.5
        const bool diag = (kb == qb);
#pragma unroll
        for (int i = 0; i < 4; i++)
#pragma unroll
            for (int j = 0; j < 4; j++) {
                if (diag && (tx * 4 + j > ty * 4 + i)) s[i][j] = -1e30f;
                else s[i][j] *= sc;
            }

        // online softmax, rows owned by (ty, i), cols spread over tx (16 lanes)
#pragma unroll
        for (int i = 0; i < 4; i++) {
            int rr = ty * 4 + i;
            float mx = fmaxf(fmaxf(s[i][0], s[i][1]), fmaxf(s[i][2], s[i][3]));
#pragma unroll
            for (int off = 1; off < 16; off <<= 1)
                mx = fmaxf(mx, __shfl_xor_sync(0xffffffffu, mx, off));

            float mo = RM[rr];
            float mn = fmaxf(mo, mx);
            float lsum = 0.0f;
#pragma unroll
            for (int j = 0; j < 4; j++) {
                float p = expf(s[i][j] - mn);
                PS[rr * 65 + tx * 4 + j] = p;
                lsum += p;
            }
#pragma unroll
            for (int off = 1; off < 16; off <<= 1)
                lsum += __shfl_xor_sync(0xffffffffu, lsum, off);

            float f = expf(mo - mn);
            if (tx == 0) {
                RM[rr]  = mn;
                RL[rr]  = RL[rr] * f + lsum;
                RSC[rr] = f;
            }
        }
        __syncthreads();

        // O += P @ V  (each thread: 8 rows (wid) x 4 cols (lane))
#pragma unroll
        for (int r8 = 0; r8 < 8; r8++) {
            int rr = wid * 8 + r8;
            float f = RSC[rr];
            float a0 = o[r8][0] * f, a1 = o[r8][1] * f;
            float a2 = o[r8][2] * f, a3 = o[r8][3] * f;
#pragma unroll 4
            for (int n = 0; n < 64; n++) {
                float p = PS[rr * 65 + n];
                float4 v = *(const float4*)&VS[n * 132 + lane * 4];
                a0 += p * v.x; a1 += p * v.y; a2 += p * v.z; a3 += p * v.w;
            }
            o[r8][0] = a0; o[r8][1] = a1; o[r8][2] = a2; o[r8][3] = a3;
        }
        __syncthreads();
    }

    // epilogue: divide by l, write [row, h*128 + col]
    float* obase = attn_out + (size_t)(b * SEQ + qb * 64) * DMODEL + h * HD;
#pragma unroll
    for (int r8 = 0; r8 < 8; r8++) {
        int rr = wid * 8 + r8;
        float inv = 1.0f / RL[rr];
        float4 out = make_float4(o[r8][0] * inv, o[r8][1] * inv,
                                 o[r8][2] * inv, o[r8][3] * inv);
        *(float4*)(obase + (size_t)rr * DMODEL + lane * 4) = out;
    }
}

// ---------------------------------------------------------------------------
// Launcher
// inputs: 0 positions(int32), 1 hidden(fp32), 2 w_qkv(fp32), 3 w_o(fp32),
//         4 q_norm_w(fp32), 5 k_norm_w(fp32). output: fp32 [B,S,D].
// ---------------------------------------------------------------------------
extern "C" void kernel_launch(void* const* d_in, const int* in_sizes, int n_in,
                              void* d_out, int out_size)
{
    (void)in_sizes; (void)n_in; (void)out_size;
    const int*   positions = (const int*)d_in[0];
    const float* hidden    = (const float*)d_in[1];
    const float* w_qkv     = (const float*)d_in[2];
    const float* w_o       = (const float*)d_in[3];
    const float* qw        = (const float*)d_in[4];
    const float* kw        = (const float*)d_in[5];
    float* out = (float*)d_out;

    float *qkv_ptr = nullptr, *attn_ptr = nullptr;
    cudaGetSymbolAddress((void**)&qkv_ptr, g_qkv);
    cudaGetSymbolAddress((void**)&attn_ptr, g_attn);

    // 1) QKV GEMM: [4096,4096] @ [4096,6144]
    {
        dim3 grid(QKVN / 128, MROWS / 128);
        gemm_kernel<<<grid, 256>>>(hidden, w_qkv, qkv_ptr, MROWS, QKVN, DMODEL);
    }

    // 2) RMSNorm + RoPE on q,k (in place)
    {
        int warps = MROWS * 40;               // 163840 warps
        int blocks = (warps * 32) / 256;      // 20480
        normrope_kernel<<<blocks, 256>>>(qkv_ptr, positions, qw, kw);
    }

    // 3) causal GQA flash attention
    {
        size_t shmem = (size_t)(64 * 132 + 128 * 65 + 64 * 132 + 64 * 65 + 192)
                       * sizeof(float);       // 118272 B
        cudaFuncSetAttribute(attn_kernel,
                             cudaFuncAttributeMaxDynamicSharedMemorySize,
                             (int)shmem);
        dim3 grid(SEQ / 64, NH, BATCH);
        attn_kernel<<<grid, 256, shmem>>>(qkv_ptr, attn_ptr);
    }

    // 4) output GEMM: [4096,4096] @ [4096,4096]
    {
        dim3 grid(DMODEL / 128, MROWS / 128);
        gemm_kernel<<<grid, 256>>>(attn_ptr, w_o, out, MROWS, DMODEL, DMODEL);
    }
}

// round 6
// speedup vs baseline: 1.6205x; 1.6205x over previous
#include <cuda_runtime.h>
#include <cuda_bf16.h>
#include <math.h>
#include <stdint.h>

// Problem constants
#define BATCH  2
#define SEQ    2048
#define DMODEL 4096
#define NH     32
#define NKV    8
#define HD     128
#define QKVN   6144           // (NH + 2*NKV) * HD
#define MROWS  4096           // BATCH * SEQ
#define KDIM   4096           // contraction dim for both big GEMMs

// GEMM tiling (mma.sync HMMA path)
#define BM 128
#define BN 128
#define BK 32                 // bf16 elems per k-chunk
#define NITER (KDIM / BK)     // 128
#define ROWB 80               // padded row stride in bytes (40 bf16) — conflict-free ldmatrix
#define TILE_B (128 * ROWB)   // 10240 bytes per (matrix,half)
#define STAGE_B (4 * TILE_B)  // Ahi,Alo,Bhi,Blo = 40960
#define GEMM_SMEM (2 * STAGE_B) // 81920

// ---------------------------------------------------------------------------
// Device global scratch (no allocation allowed)
// ---------------------------------------------------------------------------
__device__ float g_qkv[(size_t)MROWS * QKVN];
__device__ float g_attn[(size_t)MROWS * DMODEL];
__device__ __nv_bfloat16 g_ahi[(size_t)MROWS * KDIM];
__device__ __nv_bfloat16 g_alo[(size_t)MROWS * KDIM];
__device__ __nv_bfloat16 g_bqhi[(size_t)QKVN * KDIM];
__device__ __nv_bfloat16 g_bqlo[(size_t)QKVN * KDIM];
__device__ __nv_bfloat16 g_wohi[(size_t)DMODEL * KDIM];
__device__ __nv_bfloat16 g_wolo[(size_t)DMODEL * KDIM];

// ---------------------------------------------------------------------------
// helpers
// ---------------------------------------------------------------------------
__device__ __forceinline__ uint32_t smem_u32(const void* p) {
    uint32_t a;
    asm("{ .reg .u64 t; cvta.to.shared.u64 t, %1; cvt.u32.u64 %0, t; }"
        : "=r"(a) : "l"(p));
    return a;
}

__device__ __forceinline__ void ldmx4(uint32_t* r, uint32_t addr) {
    asm volatile("ldmatrix.sync.aligned.m8n8.x4.shared.b16 {%0,%1,%2,%3}, [%4];"
        : "=r"(r[0]), "=r"(r[1]), "=r"(r[2]), "=r"(r[3]) : "r"(addr));
}

__device__ __forceinline__ void mma16816(float* c, const uint32_t* a,
                                         const uint32_t* b) {
    asm volatile(
        "mma.sync.aligned.m16n8k16.row.col.f32.bf16.bf16.f32 "
        "{%0,%1,%2,%3}, {%4,%5,%6,%7}, {%8,%9}, {%0,%1,%2,%3};"
        : "+f"(c[0]), "+f"(c[1]), "+f"(c[2]), "+f"(c[3])
        : "r"(a[0]), "r"(a[1]), "r"(a[2]), "r"(a[3]), "r"(b[0]), "r"(b[1]));
}

// ---------------------------------------------------------------------------
// cp.async stage loader: A[128][32] hi/lo + B[128][32] hi/lo (B stored [N,K])
// 2048 x 16B chunks, 256 threads -> 8 per thread
// ---------------------------------------------------------------------------
__device__ __forceinline__ void load_stage(
    uint32_t sbase,
    const __nv_bfloat16* __restrict__ Ahi, const __nv_bfloat16* __restrict__ Alo,
    const __nv_bfloat16* __restrict__ Bhi, const __nv_bfloat16* __restrict__ Blo,
    int bm, int bn, int k0, int tid)
{
#pragma unroll
    for (int g8 = 0; g8 < 8; g8++) {
        int g = g8 * 256 + tid;
        int isB  = g >> 10;          // 0: A, 1: B
        int rem  = g & 1023;
        int half = rem >> 9;         // 0: hi, 1: lo
        int idx  = rem & 511;
        int row  = idx >> 2;
        int c    = idx & 3;
        const __nv_bfloat16* src;
        if (isB) src = (half ? Blo : Bhi) + (size_t)(bn + row) * KDIM + k0 + c * 8;
        else     src = (half ? Alo : Ahi) + (size_t)(bm + row) * KDIM + k0 + c * 8;
        uint32_t dst = sbase + (uint32_t)(isB * 2 + half) * TILE_B
                     + (uint32_t)(row * ROWB + c * 16);
        asm volatile("cp.async.cg.shared.global [%0], [%1], 16;"
                     :: "r"(dst), "l"(src));
    }
    asm volatile("cp.async.commit_group;" ::: "memory");
}

// ---------------------------------------------------------------------------
// HMMA GEMM: C[M,N] = A[M,K] @ B[N,K]^T, bf16 hi/lo split, fp32 accum.
// grid (N/128, M/128), 256 threads (8 warps, warp tile 32x64)
// ---------------------------------------------------------------------------
__global__ __launch_bounds__(256) void gemm_mma_kernel(
    const __nv_bfloat16* __restrict__ Ahi, const __nv_bfloat16* __restrict__ Alo,
    const __nv_bfloat16* __restrict__ Bhi, const __nv_bfloat16* __restrict__ Blo,
    float* __restrict__ C, int N)
{
    extern __shared__ __align__(128) char smem[];
    const uint32_t sb = smem_u32(smem);
    const int tid  = threadIdx.x;
    const int wid  = tid >> 5, lane = tid & 31;
    const int wm   = wid & 3;      // 0..3 -> 32-row slabs
    const int wn   = wid >> 2;     // 0..1 -> 64-col slabs
    const int bm   = blockIdx.y * BM;
    const int bn   = blockIdx.x * BN;

    float acc[2][8][4];
#pragma unroll
    for (int t = 0; t < 2; t++)
#pragma unroll
        for (int j = 0; j < 8; j++)
#pragma unroll
            for (int e = 0; e < 4; e++) acc[t][j][e] = 0.0f;

    // precomputed intra-tile ldmatrix offsets
    // A: row = wm*32 + t*16 + (lane&15), kbyte = ((lane>>4)<<3)*2
    const uint32_t a_off = (uint32_t)((wm * 32 + (lane & 15)) * ROWB
                                      + ((lane >> 4) << 4));
    // B: g = lane>>3; n = wn*64 + ((g>>1)<<3) + (lane&7); kbyte = ((g&1)<<3)*2
    const int bg = lane >> 3;
    const uint32_t b_off = (uint32_t)((wn * 64 + ((bg >> 1) << 3) + (lane & 7)) * ROWB
                                      + ((bg & 1) << 4));

    // prologue
    load_stage(sb,           Ahi, Alo, Bhi, Blo, bm, bn, 0,  tid);
    load_stage(sb + STAGE_B, Ahi, Alo, Bhi, Blo, bm, bn, BK, tid);

    for (int it = 0; it < NITER; it++) {
        if (it + 1 < NITER)
            asm volatile("cp.async.wait_group 1;" ::: "memory");
        else
            asm volatile("cp.async.wait_group 0;" ::: "memory");
        __syncthreads();

        const uint32_t st = sb + (uint32_t)(it & 1) * STAGE_B;
        const uint32_t sAhi = st,              sAlo = st + TILE_B;
        const uint32_t sBhi = st + 2 * TILE_B, sBlo = st + 3 * TILE_B;

#pragma unroll
        for (int ks = 0; ks < 2; ks++) {
            const uint32_t kb = (uint32_t)(ks * 32);  // 16 elems = 32 bytes
            uint32_t ah[2][4], al[2][4], bh[4][4], bl[4][4];
#pragma unroll
            for (int t = 0; t < 2; t++) {
                ldmx4(ah[t], sAhi + a_off + (uint32_t)(t * 16 * ROWB) + kb);
                ldmx4(al[t], sAlo + a_off + (uint32_t)(t * 16 * ROWB) + kb);
            }
#pragma unroll
            for (int jp = 0; jp < 4; jp++) {
                ldmx4(bh[jp], sBhi + b_off + (uint32_t)(jp * 16 * ROWB) + kb);
                ldmx4(bl[jp], sBlo + b_off + (uint32_t)(jp * 16 * ROWB) + kb);
            }
#pragma unroll
            for (int t = 0; t < 2; t++)
#pragma unroll
                for (int jp = 0; jp < 4; jp++) {
                    // n-tile 2*jp uses regs {0,1}; 2*jp+1 uses {2,3}
                    mma16816(acc[t][2 * jp],     ah[t], &bh[jp][0]);
                    mma16816(acc[t][2 * jp],     ah[t], &bl[jp][0]);
                    mma16816(acc[t][2 * jp],     al[t], &bh[jp][0]);
                    mma16816(acc[t][2 * jp + 1], ah[t], &bh[jp][2]);
                    mma16816(acc[t][2 * jp + 1], ah[t], &bl[jp][2]);
                    mma16816(acc[t][2 * jp + 1], al[t], &bh[jp][2]);
                }
        }
        __syncthreads();

        if (it + 2 < NITER)
            load_stage(st, Ahi, Alo, Bhi, Blo, bm, bn, (it + 2) * BK, tid);
    }

    // epilogue: acc -> C
    const int r0  = bm + wm * 32 + (lane >> 2);
    const int cc0 = bn + wn * 64 + 2 * (lane & 3);
#pragma unroll
    for (int t = 0; t < 2; t++) {
#pragma unroll
        for (int j = 0; j < 8; j++) {
            float* p0 = C + (size_t)(r0 + t * 16)     * N + cc0 + j * 8;
            float* p1 = C + (size_t)(r0 + t * 16 + 8) * N + cc0 + j * 8;
            *(float2*)p0 = make_float2(acc[t][j][0], acc[t][j][1]);
            *(float2*)p1 = make_float2(acc[t][j][2], acc[t][j][3]);
        }
    }
}

// ---------------------------------------------------------------------------
// fp32 -> bf16 hi/lo split (same layout)
// ---------------------------------------------------------------------------
__global__ __launch_bounds__(256) void split_kernel(
    const float* __restrict__ in, __nv_bfloat16* __restrict__ hi,
    __nv_bfloat16* __restrict__ lo, size_t n4)
{
    size_t i = (size_t)blockIdx.x * blockDim.x + threadIdx.x;
    size_t stride = (size_t)gridDim.x * blockDim.x;
    for (; i < n4; i += stride) {
        float4 v = ((const float4*)in)[i];
        float f[4] = { v.x, v.y, v.z, v.w };
        unsigned short hs[4], ls[4];
#pragma unroll
        for (int j = 0; j < 4; j++) {
            __nv_bfloat16 hb = __float2bfloat16(f[j]);
            __nv_bfloat16 lb = __float2bfloat16(f[j] - __bfloat162float(hb));
            hs[j] = __bfloat16_as_ushort(hb);
            ls[j] = __bfloat16_as_ushort(lb);
        }
        ((ushort4*)hi)[i] = make_ushort4(hs[0], hs[1], hs[2], hs[3]);
        ((ushort4*)lo)[i] = make_ushort4(ls[0], ls[1], ls[2], ls[3]);
    }
}

// ---------------------------------------------------------------------------
// fp32 [R,C] -> transposed bf16 hi/lo [C,R]; block (32,8), grid (C/32, R/32)
// ---------------------------------------------------------------------------
__global__ __launch_bounds__(256) void split_T_kernel(
    const float* __restrict__ in, __nv_bfloat16* __restrict__ hiT,
    __nv_bfloat16* __restrict__ loT, int R, int C)
{
    __shared__ float t[32][33];
    int c0 = blockIdx.x * 32, r0 = blockIdx.y * 32;
    int tx = threadIdx.x, ty = threadIdx.y;
#pragma unroll
    for (int i = 0; i < 4; i++)
        t[ty + i * 8][tx] = in[(size_t)(r0 + ty + i * 8) * C + c0 + tx];
    __syncthreads();
#pragma unroll
    for (int i = 0; i < 4; i++) {
        float v = t[tx][ty + i * 8];
        __nv_bfloat16 hb = __float2bfloat16(v);
        __nv_bfloat16 lb = __float2bfloat16(v - __bfloat162float(hb));
        size_t o = (size_t)(c0 + ty + i * 8) * R + r0 + tx;
        hiT[o] = hb;
        loT[o] = lb;
    }
}

// ---------------------------------------------------------------------------
// Fused per-head RMSNorm + NeoX RoPE (unchanged, passing)
// ---------------------------------------------------------------------------
__global__ __launch_bounds__(256) void normrope_kernel(
    float* __restrict__ qkv, const int* __restrict__ positions,
    const float* __restrict__ qw, const float* __restrict__ kw)
{
    int gw = (blockIdx.x * blockDim.x + threadIdx.x) >> 5;
    int lane = threadIdx.x & 31;
    int row = gw / 40;
    int head = gw - row * 40;
    if (row >= MROWS) return;

    const float* w = (head < 32) ? qw : kw;
    float* ptr = qkv + (size_t)row * QKVN + head * HD;

    float x0 = ptr[lane];
    float x1 = ptr[lane + 32];
    float x2 = ptr[lane + 64];
    float x3 = ptr[lane + 96];

    float ss = x0 * x0 + x1 * x1 + x2 * x2 + x3 * x3;
#pragma unroll
    for (int off = 1; off < 32; off <<= 1)
        ss += __shfl_xor_sync(0xffffffffu, ss, off);

    float r = rsqrtf(ss * (1.0f / 128.0f) + 1e-6f);
    x0 = x0 * r * w[lane];
    x1 = x1 * r * w[lane + 32];
    x2 = x2 * r * w[lane + 64];
    x3 = x3 * r * w[lane + 96];

    float pf = (float)positions[row];
    float inv0 = powf(10000.0f, -((float)(2 * lane)) / 128.0f);
    float inv1 = powf(10000.0f, -((float)(2 * (lane + 32))) / 128.0f);
    float s0, c0, s1, c1;
    sincosf(pf * inv0, &s0, &c0);
    sincosf(pf * inv1, &s1, &c1);

    float y0 = x0 * c0 - x2 * s0;
    float y2 = x2 * c0 + x0 * s0;
    float y1 = x1 * c1 - x3 * s1;
    float y3 = x3 * c1 + x1 * s1;

    ptr[lane]      = y0;
    ptr[lane + 32] = y1;
    ptr[lane + 64] = y2;
    ptr[lane + 96] = y3;
}

// ---------------------------------------------------------------------------
// Causal GQA flash attention, fp32 (unchanged, passing)
// ---------------------------------------------------------------------------
__global__ __launch_bounds__(256) void attn_kernel(
    const float* __restrict__ qkv, float* __restrict__ attn_out)
{
    extern __shared__ float sm[];
    float* QS  = sm;
    float* KS  = QS + 64 * 132;
    float* VS  = KS + 128 * 65;
    float* PS  = VS + 64 * 132;
    float* RM  = PS + 64 * 65;
    float* RL  = RM + 64;
    float* RSC = RL + 64;

    const int tid = threadIdx.x;
    const int qb = blockIdx.x;
    const int h  = blockIdx.y;
    const int b  = blockIdx.z;
    const int kh = h >> 2;

    const float* qbase = qkv + (size_t)(b * SEQ + qb * 64) * QKVN + h * HD;
    const float* kbase = qkv + (size_t)(b * SEQ) * QKVN + NH * HD + kh * HD;
    const float* vbase = qkv + (size_t)(b * SEQ) * QKVN + (NH + NKV) * HD + kh * HD;

#pragma unroll
    for (int i = 0; i < 8; i++) {
        int idx = i * 256 + tid;
        int rr = idx >> 5, c4 = idx & 31;
        float4 v = *(const float4*)(qbase + (size_t)rr * QKVN + c4 * 4);
        *(float4*)&QS[rr * 132 + c4 * 4] = v;
    }
    if (tid < 64) { RM[tid] = -1e30f; RL[tid] = 0.0f; }

    const int wid = tid >> 5, lane = tid & 31;
    const int ty  = tid >> 4, tx   = tid & 15;

    float o[8][4];
#pragma unroll
    for (int i = 0; i < 8; i++)
#pragma unroll
        for (int j = 0; j < 4; j++) o[i][j] = 0.0f;

    __syncthreads();

    for (int kb = 0; kb <= qb; kb++) {
#pragma unroll
        for (int i = 0; i < 8; i++) {
            int idx = i * 256 + tid;
            int n = idx >> 5, c4 = idx & 31;
            const float* kr = kbase + (size_t)(kb * 64 + n) * QKVN + c4 * 4;
            float4 kv = *(const float4*)kr;
            KS[(c4 * 4 + 0) * 65 + n] = kv.x;
            KS[(c4 * 4 + 1) * 65 + n] = kv.y;
            KS[(c4 * 4 + 2) * 65 + n] = kv.z;
            KS[(c4 * 4 + 3) * 65 + n] = kv.w;
            const float* vr = vbase + (size_t)(kb * 64 + n) * QKVN + c4 * 4;
            *(float4*)&VS[n * 132 + c4 * 4] = *(const float4*)vr;
        }
        __syncthreads();

        float s[4][4];
#pragma unroll
        for (int i = 0; i < 4; i++)
#pragma unroll
            for (int j = 0; j < 4; j++) s[i][j] = 0.0f;

#pragma unroll 4
        for (int d = 0; d < 128; d++) {
            float qv[4], kv[4];
#pragma unroll
            for (int i = 0; i < 4; i++) qv[i] = QS[(ty * 4 + i) * 132 + d];
#pragma unroll
            for (int j = 0; j < 4; j++) kv[j] = KS[d * 65 + tx * 4 + j];
#pragma unroll
            for (int i = 0; i < 4; i++)
#pragma unroll
                for (int j = 0; j < 4; j++)
                    s[i][j] += qv[i] * kv[j];
        }

        const float sc = 0.08838834764831845f;
        const bool diag = (kb == qb);
#pragma unroll
        for (int i = 0; i < 4; i++)
#pragma unroll
            for (int j = 0; j < 4; j++) {
                if (diag && (tx * 4 + j > ty * 4 + i)) s[i][j] = -1e30f;
                else s[i][j] *= sc;
            }

#pragma unroll
        for (int i = 0; i < 4; i++) {
            int rr = ty * 4 + i;
            float mx = fmaxf(fmaxf(s[i][0], s[i][1]), fmaxf(s[i][2], s[i][3]));
#pragma unroll
            for (int off = 1; off < 16; off <<= 1)
                mx = fmaxf(mx, __shfl_xor_sync(0xffffffffu, mx, off));

            float mo = RM[rr];
            float mn = fmaxf(mo, mx);
            float lsum = 0.0f;
#pragma unroll
            for (int j = 0; j < 4; j++) {
                float p = expf(s[i][j] - mn);
                PS[rr * 65 + tx * 4 + j] = p;
                lsum += p;
            }
#pragma unroll
            for (int off = 1; off < 16; off <<= 1)
                lsum += __shfl_xor_sync(0xffffffffu, lsum, off);

            float f = expf(mo - mn);
            if (tx == 0) {
                RM[rr]  = mn;
                RL[rr]  = RL[rr] * f + lsum;
                RSC[rr] = f;
            }
        }
        __syncthreads();

#pragma unroll
        for (int r8 = 0; r8 < 8; r8++) {
            int rr = wid * 8 + r8;
            float f = RSC[rr];
            float a0 = o[r8][0] * f, a1 = o[r8][1] * f;
            float a2 = o[r8][2] * f, a3 = o[r8][3] * f;
#pragma unroll 4
            for (int n = 0; n < 64; n++) {
                float p = PS[rr * 65 + n];
                float4 v = *(const float4*)&VS[n * 132 + lane * 4];
                a0 += p * v.x; a1 += p * v.y; a2 += p * v.z; a3 += p * v.w;
            }
            o[r8][0] = a0; o[r8][1] = a1; o[r8][2] = a2; o[r8][3] = a3;
        }
        __syncthreads();
    }

    float* obase = attn_out + (size_t)(b * SEQ + qb * 64) * DMODEL + h * HD;
#pragma unroll
    for (int r8 = 0; r8 < 8; r8++) {
        int rr = wid * 8 + r8;
        float inv = 1.0f / RL[rr];
        float4 out = make_float4(o[r8][0] * inv, o[r8][1] * inv,
                                 o[r8][2] * inv, o[r8][3] * inv);
        *(float4*)(obase + (size_t)rr * DMODEL + lane * 4) = out;
    }
}

// ---------------------------------------------------------------------------
// Launcher
// ---------------------------------------------------------------------------
extern "C" void kernel_launch(void* const* d_in, const int* in_sizes, int n_in,
                              void* d_out, int out_size)
{
    (void)in_sizes; (void)n_in; (void)out_size;
    const int*   positions = (const int*)d_in[0];
    const float* hidden    = (const float*)d_in[1];
    const float* w_qkv     = (const float*)d_in[2];
    const float* w_o       = (const float*)d_in[3];
    const float* qw        = (const float*)d_in[4];
    const float* kw        = (const float*)d_in[5];
    float* out = (float*)d_out;

    float *qkv_ptr, *attn_ptr;
    __nv_bfloat16 *ahi, *alo, *bqhi, *bqlo, *wohi, *wolo;
    cudaGetSymbolAddress((void**)&qkv_ptr,  g_qkv);
    cudaGetSymbolAddress((void**)&attn_ptr, g_attn);
    cudaGetSymbolAddress((void**)&ahi,  g_ahi);
    cudaGetSymbolAddress((void**)&alo,  g_alo);
    cudaGetSymbolAddress((void**)&bqhi, g_bqhi);
    cudaGetSymbolAddress((void**)&bqlo, g_bqlo);
    cudaGetSymbolAddress((void**)&wohi, g_wohi);
    cudaGetSymbolAddress((void**)&wolo, g_wolo);

    cudaFuncSetAttribute(gemm_mma_kernel,
        cudaFuncAttributeMaxDynamicSharedMemorySize, GEMM_SMEM);
    cudaFuncSetAttribute(attn_kernel,
        cudaFuncAttributeMaxDynamicSharedMemorySize, 118272);

    // 1) prep: split activations, split+transpose weights
    split_kernel<<<4096, 256>>>(hidden, ahi, alo, (size_t)MROWS * KDIM / 4);
    {
        dim3 g(QKVN / 32, KDIM / 32), b(32, 8);
        split_T_kernel<<<g, b>>>(w_qkv, bqhi, bqlo, KDIM, QKVN);
    }
    {
        dim3 g(DMODEL / 32, KDIM / 32), b(32, 8);
        split_T_kernel<<<g, b>>>(w_o, wohi, wolo, KDIM, DMODEL);
    }

    // 2) QKV GEMM (HMMA): [4096,4096] @ [6144,4096]^T
    {
        dim3 grid(QKVN / BN, MROWS / BM);
        gemm_mma_kernel<<<grid, 256, GEMM_SMEM>>>(ahi, alo, bqhi, bqlo,
                                                  qkv_ptr, QKVN);
    }

    // 3) RMSNorm + RoPE
    normrope_kernel<<<20480, 256>>>(qkv_ptr, positions, qw, kw);

    // 4) causal GQA flash attention (fp32)
    {
        dim3 grid(SEQ / 64, NH, BATCH);
        attn_kernel<<<grid, 256, 118272>>>(qkv_ptr, attn_ptr);
    }

    // 5) split attention output, then O GEMM (HMMA)
    split_kernel<<<4096, 256>>>(attn_ptr, ahi, alo, (size_t)MROWS * KDIM / 4);
    {
        dim3 grid(DMODEL / BN, MROWS / BM);
        gemm_mma_kernel<<<grid, 256, GEMM_SMEM>>>(ahi, alo, wohi, wolo,
                                                  out, DMODEL);
    }
}

// round 7
// speedup vs baseline: 3.0088x; 1.8567x over previous
#include <cuda_runtime.h>
#include <cuda_bf16.h>
#include <math.h>
#include <stdint.h>

// Problem constants
#define BATCH  2
#define SEQ    2048
#define DMODEL 4096
#define NH     32
#define NKV    8
#define HD     128
#define QKVN   6144
#define MROWS  4096
#define KDIM   4096
#define SCALE  0.08838834764831845f

// GEMM tiling (unchanged from passing R6)
#define BM 128
#define BN 128
#define BK 32
#define NITER (KDIM / BK)
#define ROWB 80
#define TILE_B (128 * ROWB)
#define STAGE_B (4 * TILE_B)
#define GEMM_SMEM (2 * STAGE_B)

// Attention smem layout (bytes): Qhi,Qlo,Khi,Klo = 64x136 bf16 rows (272B);
// VThi,VTlo = 128x72 bf16 rows (144B)
#define AQ_HI 0
#define AQ_LO 17408
#define AK_HI 34816
#define AK_LO 52224
#define AV_HI 69632
#define AV_LO 88064
#define ATT_SMEM 106496

// ---------------------------------------------------------------------------
// Device global scratch
// ---------------------------------------------------------------------------
__device__ float g_qkv[(size_t)MROWS * QKVN];
__device__ __nv_bfloat16 g_ahi[(size_t)MROWS * KDIM];   // hidden split, later Q hi
__device__ __nv_bfloat16 g_alo[(size_t)MROWS * KDIM];
__device__ __nv_bfloat16 g_bqhi[(size_t)QKVN * KDIM];
__device__ __nv_bfloat16 g_bqlo[(size_t)QKVN * KDIM];
__device__ __nv_bfloat16 g_wohi[(size_t)DMODEL * KDIM];
__device__ __nv_bfloat16 g_wolo[(size_t)DMODEL * KDIM];
__device__ __nv_bfloat16 g_khi[(size_t)MROWS * NKV * HD];
__device__ __nv_bfloat16 g_klo[(size_t)MROWS * NKV * HD];
__device__ __nv_bfloat16 g_vhi[(size_t)MROWS * NKV * HD];
__device__ __nv_bfloat16 g_vlo[(size_t)MROWS * NKV * HD];
__device__ __nv_bfloat16 g_ohi[(size_t)MROWS * DMODEL]; // attention out hi/lo
__device__ __nv_bfloat16 g_olo[(size_t)MROWS * DMODEL];

// ---------------------------------------------------------------------------
// helpers
// ---------------------------------------------------------------------------
__device__ __forceinline__ uint32_t smem_u32(const void* p) {
    uint32_t a;
    asm("{ .reg .u64 t; cvta.to.shared.u64 t, %1; cvt.u32.u64 %0, t; }"
        : "=r"(a) : "l"(p));
    return a;
}

__device__ __forceinline__ void ldmx4(uint32_t* r, uint32_t addr) {
    asm volatile("ldmatrix.sync.aligned.m8n8.x4.shared.b16 {%0,%1,%2,%3}, [%4];"
        : "=r"(r[0]), "=r"(r[1]), "=r"(r[2]), "=r"(r[3]) : "r"(addr));
}

__device__ __forceinline__ void mma16816(float* c, const uint32_t* a,
                                         const uint32_t* b) {
    asm volatile(
        "mma.sync.aligned.m16n8k16.row.col.f32.bf16.bf16.f32 "
        "{%0,%1,%2,%3}, {%4,%5,%6,%7}, {%8,%9}, {%0,%1,%2,%3};"
        : "+f"(c[0]), "+f"(c[1]), "+f"(c[2]), "+f"(c[3])
        : "r"(a[0]), "r"(a[1]), "r"(a[2]), "r"(a[3]), "r"(b[0]), "r"(b[1]));
}

// pack two floats into bf16x2 hi word, emitting lo word (residual) too
__device__ __forceinline__ uint32_t pack_hilo(float x, float y, uint32_t& lo) {
    __nv_bfloat16 hx = __float2bfloat16(x);
    __nv_bfloat16 hy = __float2bfloat16(y);
    __nv_bfloat16 lx = __float2bfloat16(x - __bfloat162float(hx));
    __nv_bfloat16 ly = __float2bfloat16(y - __bfloat162float(hy));
    lo = ((uint32_t)__bfloat16_as_ushort(ly) << 16) | __bfloat16_as_ushort(lx);
    return ((uint32_t)__bfloat16_as_ushort(hy) << 16) | __bfloat16_as_ushort(hx);
}

// ---------------------------------------------------------------------------
// GEMM stage loader (unchanged)
// ---------------------------------------------------------------------------
__device__ __forceinline__ void load_stage(
    uint32_t sbase,
    const __nv_bfloat16* __restrict__ Ahi, const __nv_bfloat16* __restrict__ Alo,
    const __nv_bfloat16* __restrict__ Bhi, const __nv_bfloat16* __restrict__ Blo,
    int bm, int bn, int k0, int tid)
{
#pragma unroll
    for (int g8 = 0; g8 < 8; g8++) {
        int g = g8 * 256 + tid;
        int isB  = g >> 10;
        int rem  = g & 1023;
        int half = rem >> 9;
        int idx  = rem & 511;
        int row  = idx >> 2;
        int c    = idx & 3;
        const __nv_bfloat16* src;
        if (isB) src = (half ? Blo : Bhi) + (size_t)(bn + row) * KDIM + k0 + c * 8;
        else     src = (half ? Alo : Ahi) + (size_t)(bm + row) * KDIM + k0 + c * 8;
        uint32_t dst = sbase + (uint32_t)(isB * 2 + half) * TILE_B
                     + (uint32_t)(row * ROWB + c * 16);
        asm volatile("cp.async.cg.shared.global [%0], [%1], 16;"
                     :: "r"(dst), "l"(src));
    }
    asm volatile("cp.async.commit_group;" ::: "memory");
}

// ---------------------------------------------------------------------------
// HMMA GEMM (unchanged from passing R6)
// ---------------------------------------------------------------------------
__global__ __launch_bounds__(256) void gemm_mma_kernel(
    const __nv_bfloat16* __restrict__ Ahi, const __nv_bfloat16* __restrict__ Alo,
    const __nv_bfloat16* __restrict__ Bhi, const __nv_bfloat16* __restrict__ Blo,
    float* __restrict__ C, int N)
{
    extern __shared__ __align__(128) char smem[];
    const uint32_t sb = smem_u32(smem);
    const int tid  = threadIdx.x;
    const int wid  = tid >> 5, lane = tid & 31;
    const int wm   = wid & 3;
    const int wn   = wid >> 2;
    const int bm   = blockIdx.y * BM;
    const int bn   = blockIdx.x * BN;

    float acc[2][8][4];
#pragma unroll
    for (int t = 0; t < 2; t++)
#pragma unroll
        for (int j = 0; j < 8; j++)
#pragma unroll
            for (int e = 0; e < 4; e++) acc[t][j][e] = 0.0f;

    const uint32_t a_off = (uint32_t)((wm * 32 + (lane & 15)) * ROWB
                                      + ((lane >> 4) << 4));
    const int bg = lane >> 3;
    const uint32_t b_off = (uint32_t)((wn * 64 + ((bg >> 1) << 3) + (lane & 7)) * ROWB
                                      + ((bg & 1) << 4));

    load_stage(sb,           Ahi, Alo, Bhi, Blo, bm, bn, 0,  tid);
    load_stage(sb + STAGE_B, Ahi, Alo, Bhi, Blo, bm, bn, BK, tid);

    for (int it = 0; it < NITER; it++) {
        if (it + 1 < NITER)
            asm volatile("cp.async.wait_group 1;" ::: "memory");
        else
            asm volatile("cp.async.wait_group 0;" ::: "memory");
        __syncthreads();

        const uint32_t st = sb + (uint32_t)(it & 1) * STAGE_B;
        const uint32_t sAhi = st,              sAlo = st + TILE_B;
        const uint32_t sBhi = st + 2 * TILE_B, sBlo = st + 3 * TILE_B;

#pragma unroll
        for (int ks = 0; ks < 2; ks++) {
            const uint32_t kb = (uint32_t)(ks * 32);
            uint32_t ah[2][4], al[2][4], bh[4][4], bl[4][4];
#pragma unroll
            for (int t = 0; t < 2; t++) {
                ldmx4(ah[t], sAhi + a_off + (uint32_t)(t * 16 * ROWB) + kb);
                ldmx4(al[t], sAlo + a_off + (uint32_t)(t * 16 * ROWB) + kb);
            }
#pragma unroll
            for (int jp = 0; jp < 4; jp++) {
                ldmx4(bh[jp], sBhi + b_off + (uint32_t)(jp * 16 * ROWB) + kb);
                ldmx4(bl[jp], sBlo + b_off + (uint32_t)(jp * 16 * ROWB) + kb);
            }
#pragma unroll
            for (int t = 0; t < 2; t++)
#pragma unroll
                for (int jp = 0; jp < 4; jp++) {
                    mma16816(acc[t][2 * jp],     ah[t], &bh[jp][0]);
                    mma16816(acc[t][2 * jp],     ah[t], &bl[jp][0]);
                    mma16816(acc[t][2 * jp],     al[t], &bh[jp][0]);
                    mma16816(acc[t][2 * jp + 1], ah[t], &bh[jp][2]);
                    mma16816(acc[t][2 * jp + 1], ah[t], &bl[jp][2]);
                    mma16816(acc[t][2 * jp + 1], al[t], &bh[jp][2]);
                }
        }
        __syncthreads();

        if (it + 2 < NITER)
            load_stage(st, Ahi, Alo, Bhi, Blo, bm, bn, (it + 2) * BK, tid);
    }

    const int r0  = bm + wm * 32 + (lane >> 2);
    const int cc0 = bn + wn * 64 + 2 * (lane & 3);
#pragma unroll
    for (int t = 0; t < 2; t++) {
#pragma unroll
        for (int j = 0; j < 8; j++) {
            float* p0 = C + (size_t)(r0 + t * 16)     * N + cc0 + j * 8;
            float* p1 = C + (size_t)(r0 + t * 16 + 8) * N + cc0 + j * 8;
            *(float2*)p0 = make_float2(acc[t][j][0], acc[t][j][1]);
            *(float2*)p1 = make_float2(acc[t][j][2], acc[t][j][3]);
        }
    }
}

// ---------------------------------------------------------------------------
// fp32 -> bf16 hi/lo split
// ---------------------------------------------------------------------------
__global__ __launch_bounds__(256) void split_kernel(
    const float* __restrict__ in, __nv_bfloat16* __restrict__ hi,
    __nv_bfloat16* __restrict__ lo, size_t n4)
{
    size_t i = (size_t)blockIdx.x * blockDim.x + threadIdx.x;
    size_t stride = (size_t)gridDim.x * blockDim.x;
    for (; i < n4; i += stride) {
        float4 v = ((const float4*)in)[i];
        float f[4] = { v.x, v.y, v.z, v.w };
        unsigned short hs[4], ls[4];
#pragma unroll
        for (int j = 0; j < 4; j++) {
            __nv_bfloat16 hb = __float2bfloat16(f[j]);
            __nv_bfloat16 lb = __float2bfloat16(f[j] - __bfloat162float(hb));
            hs[j] = __bfloat16_as_ushort(hb);
            ls[j] = __bfloat16_as_ushort(lb);
        }
        ((ushort4*)hi)[i] = make_ushort4(hs[0], hs[1], hs[2], hs[3]);
        ((ushort4*)lo)[i] = make_ushort4(ls[0], ls[1], ls[2], ls[3]);
    }
}

// fp32 [R,C] -> transposed bf16 hi/lo [C,R]
__global__ __launch_bounds__(256) void split_T_kernel(
    const float* __restrict__ in, __nv_bfloat16* __restrict__ hiT,
    __nv_bfloat16* __restrict__ loT, int R, int C)
{
    __shared__ float t[32][33];
    int c0 = blockIdx.x * 32, r0 = blockIdx.y * 32;
    int tx = threadIdx.x, ty = threadIdx.y;
#pragma unroll
    for (int i = 0; i < 4; i++)
        t[ty + i * 8][tx] = in[(size_t)(r0 + ty + i * 8) * C + c0 + tx];
    __syncthreads();
#pragma unroll
    for (int i = 0; i < 4; i++) {
        float v = t[tx][ty + i * 8];
        __nv_bfloat16 hb = __float2bfloat16(v);
        __nv_bfloat16 lb = __float2bfloat16(v - __bfloat162float(hb));
        size_t o = (size_t)(c0 + ty + i * 8) * R + r0 + tx;
        hiT[o] = hb;
        loT[o] = lb;
    }
}

// ---------------------------------------------------------------------------
// Fused RMSNorm + RoPE + bf16 hi/lo pack. 48 heads/row: 0-31 q, 32-39 k, 40-47 v
// ---------------------------------------------------------------------------
__global__ __launch_bounds__(256) void normrope_pack_kernel(
    const float* __restrict__ qkv, const int* __restrict__ positions,
    const float* __restrict__ qw, const float* __restrict__ kw,
    __nv_bfloat16* __restrict__ Qhi, __nv_bfloat16* __restrict__ Qlo,
    __nv_bfloat16* __restrict__ Khi, __nv_bfloat16* __restrict__ Klo,
    __nv_bfloat16* __restrict__ Vhi, __nv_bfloat16* __restrict__ Vlo)
{
    int gw = (blockIdx.x * blockDim.x + threadIdx.x) >> 5;
    int lane = threadIdx.x & 31;
    int row = gw / 48;
    int head = gw - row * 48;
    if (row >= MROWS) return;

    const float* ptr = qkv + (size_t)row * QKVN + head * HD;
    float y0 = ptr[lane];
    float y1 = ptr[lane + 32];
    float y2 = ptr[lane + 64];
    float y3 = ptr[lane + 96];

    if (head < 40) {
        const float* w = (head < 32) ? qw : kw;
        float ss = y0 * y0 + y1 * y1 + y2 * y2 + y3 * y3;
#pragma unroll
        for (int off = 1; off < 32; off <<= 1)
            ss += __shfl_xor_sync(0xffffffffu, ss, off);
        float r = rsqrtf(ss * (1.0f / 128.0f) + 1e-6f);
        float x0 = y0 * r * w[lane];
        float x1 = y1 * r * w[lane + 32];
        float x2 = y2 * r * w[lane + 64];
        float x3 = y3 * r * w[lane + 96];

        float pf = (float)positions[row];
        float inv0 = powf(10000.0f, -((float)(2 * lane)) / 128.0f);
        float inv1 = powf(10000.0f, -((float)(2 * (lane + 32))) / 128.0f);
        float s0, c0, s1, c1;
        sincosf(pf * inv0, &s0, &c0);
        sincosf(pf * inv1, &s1, &c1);

        y0 = x0 * c0 - x2 * s0;
        y2 = x2 * c0 + x0 * s0;
        y1 = x1 * c1 - x3 * s1;
        y3 = x3 * c1 + x1 * s1;
    }

    __nv_bfloat16 *hi, *lo;
    size_t off;
    if (head < 32)      { hi = Qhi; lo = Qlo; off = (size_t)row * 4096 + head * 128; }
    else if (head < 40) { hi = Khi; lo = Klo; off = (size_t)row * 1024 + (head - 32) * 128; }
    else                { hi = Vhi; lo = Vlo; off = (size_t)row * 1024 + (head - 40) * 128; }

    float ys[4] = { y0, y1, y2, y3 };
#pragma unroll
    for (int k = 0; k < 4; k++) {
        __nv_bfloat16 hb = __float2bfloat16(ys[k]);
        __nv_bfloat16 lb = __float2bfloat16(ys[k] - __bfloat162float(hb));
        hi[off + lane + k * 32] = hb;
        lo[off + lane + k * 32] = lb;
    }
}

// ---------------------------------------------------------------------------
// HMMA causal GQA flash attention, bf16 hi/lo, fp32 softmax.
// grid (S/64, NH, BATCH), 128 threads (4 warps, 16 query rows each).
// ---------------------------------------------------------------------------
__global__ __launch_bounds__(128, 2) void attn_mma_kernel(
    const __nv_bfloat16* __restrict__ Qhi, const __nv_bfloat16* __restrict__ Qlo,
    const __nv_bfloat16* __restrict__ Khi, const __nv_bfloat16* __restrict__ Klo,
    const __nv_bfloat16* __restrict__ Vhi, const __nv_bfloat16* __restrict__ Vlo,
    __nv_bfloat16* __restrict__ Ohi, __nv_bfloat16* __restrict__ Olo)
{
    extern __shared__ __align__(128) char asmem[];
    const uint32_t sb = smem_u32(asmem);
    const uint32_t sQh = sb + AQ_HI, sQl = sb + AQ_LO;
    const uint32_t sKh = sb + AK_HI, sKl = sb + AK_LO;
    const uint32_t sVh = sb + AV_HI, sVl = sb + AV_LO;
    char* pVh = asmem + AV_HI;
    char* pVl = asmem + AV_LO;

    const int tid = threadIdx.x, wid = tid >> 5, lane = tid & 31;
    const int qb = blockIdx.x, h = blockIdx.y, b = blockIdx.z, kh = h >> 2;
    const size_t qrow0 = (size_t)(b * SEQ + qb * 64);

    // Q tile (hi+lo) via cp.async
    for (int t = tid; t < 2048; t += 128) {
        int half = t >> 10, r = (t >> 4) & 63, c = t & 15;
        const __nv_bfloat16* src = (half ? Qlo : Qhi)
            + (qrow0 + r) * 4096 + (size_t)h * 128 + c * 8;
        uint32_t dst = (half ? sQl : sQh) + (uint32_t)(r * 272 + c * 16);
        asm volatile("cp.async.cg.shared.global [%0], [%1], 16;"
                     :: "r"(dst), "l"(src));
    }
    asm volatile("cp.async.commit_group;" ::: "memory");

    const uint32_t a_off = (uint32_t)((wid * 16 + (lane & 15)) * 272
                                      + ((lane >> 4) * 16));
    const int bg = lane >> 3;
    const uint32_t kfrag = (uint32_t)(((((bg >> 1) << 3) + (lane & 7)) * 272)
                                      + ((bg & 1) * 16));
    const uint32_t vfrag = (uint32_t)(((((bg >> 1) << 3) + (lane & 7)) * 144)
                                      + ((bg & 1) * 16));
    const int r = lane >> 2;
    const int qg0 = qb * 64 + wid * 16 + r;
    const int colq = 2 * (lane & 3);

    float oacc[16][4];
#pragma unroll
    for (int jj = 0; jj < 16; jj++)
#pragma unroll
        for (int e = 0; e < 4; e++) oacc[jj][e] = 0.0f;
    float m0 = -1e30f, m1 = -1e30f, l0 = 0.0f, l1 = 0.0f;

    asm volatile("cp.async.wait_group 0;" ::: "memory");
    __syncthreads();

    for (int kb = 0; kb <= qb; kb++) {
        const size_t krow0 = (size_t)(b * SEQ + kb * 64);
        // K tile (hi+lo) via cp.async
        for (int t = tid; t < 2048; t += 128) {
            int half = t >> 10, rr = (t >> 4) & 63, c = t & 15;
            const __nv_bfloat16* src = (half ? Klo : Khi)
                + (krow0 + rr) * 1024 + (size_t)kh * 128 + c * 8;
            uint32_t dst = (half ? sKl : sKh) + (uint32_t)(rr * 272 + c * 16);
            asm volatile("cp.async.cg.shared.global [%0], [%1], 16;"
                         :: "r"(dst), "l"(src));
        }
        asm volatile("cp.async.commit_group;" ::: "memory");
        // V tile transposed into smem: VT[d][key]
        for (int t = tid; t < 2048; t += 128) {
            int half = t >> 10, idx = t & 1023;
            int key = idx & 63, db = idx >> 6;
            const __nv_bfloat16* src = (half ? Vlo : Vhi)
                + (krow0 + key) * 1024 + (size_t)kh * 128 + db * 8;
            union { uint4 u; __nv_bfloat16 e[8]; } vv;
            vv.u = *(const uint4*)src;
            char* base = (half ? pVl : pVh) + key * 2 + db * 8 * 144;
#pragma unroll
            for (int i = 0; i < 8; i++)
                *(__nv_bfloat16*)(base + i * 144) = vv.e[i];
        }
        asm volatile("cp.async.wait_group 0;" ::: "memory");
        __syncthreads();

        // S = Q @ K^T (3-term hi/lo)
        float sacc[8][4];
#pragma unroll
        for (int j = 0; j < 8; j++)
#pragma unroll
            for (int e = 0; e < 4; e++) sacc[j][e] = 0.0f;

#pragma unroll
        for (int ks = 0; ks < 8; ks++) {
            uint32_t qh4[4], ql4[4];
            ldmx4(qh4, sQh + a_off + (uint32_t)(ks * 32));
            ldmx4(ql4, sQl + a_off + (uint32_t)(ks * 32));
#pragma unroll
            for (int j = 0; j < 4; j++) {
                uint32_t k4h[4], k4l[4];
                ldmx4(k4h, sKh + kfrag + (uint32_t)(j * 16 * 272 + ks * 32));
                ldmx4(k4l, sKl + kfrag + (uint32_t)(j * 16 * 272 + ks * 32));
                mma16816(sacc[2 * j],     qh4, &k4h[0]);
                mma16816(sacc[2 * j],     qh4, &k4l[0]);
                mma16816(sacc[2 * j],     ql4, &k4h[0]);
                mma16816(sacc[2 * j + 1], qh4, &k4h[2]);
                mma16816(sacc[2 * j + 1], qh4, &k4l[2]);
                mma16816(sacc[2 * j + 1], ql4, &k4h[2]);
            }
        }

        // scale + causal mask
        const bool diag = (kb == qb);
#pragma unroll
        for (int j = 0; j < 8; j++) {
            int cg = kb * 64 + j * 8 + colq;
#pragma unroll
            for (int e = 0; e < 4; e++) {
                int rg = qg0 + ((e >> 1) << 3);
                if (diag && (cg + (e & 1)) > rg) sacc[j][e] = -1e30f;
                else sacc[j][e] *= SCALE;
            }
        }

        // online softmax (rows r, r+8; quad-reduce over lane&3)
        float mx0 = -1e30f, mx1 = -1e30f;
#pragma unroll
        for (int j = 0; j < 8; j++) {
            mx0 = fmaxf(mx0, fmaxf(sacc[j][0], sacc[j][1]));
            mx1 = fmaxf(mx1, fmaxf(sacc[j][2], sacc[j][3]));
        }
        mx0 = fmaxf(mx0, __shfl_xor_sync(0xffffffffu, mx0, 1));
        mx0 = fmaxf(mx0, __shfl_xor_sync(0xffffffffu, mx0, 2));
        mx1 = fmaxf(mx1, __shfl_xor_sync(0xffffffffu, mx1, 1));
        mx1 = fmaxf(mx1, __shfl_xor_sync(0xffffffffu, mx1, 2));

        float mn0 = fmaxf(m0, mx0), mn1 = fmaxf(m1, mx1);
        float al0 = __expf(m0 - mn0), al1 = __expf(m1 - mn1);
        float ps0 = 0.0f, ps1 = 0.0f;
#pragma unroll
        for (int j = 0; j < 8; j++) {
            sacc[j][0] = __expf(sacc[j][0] - mn0); ps0 += sacc[j][0];
            sacc[j][1] = __expf(sacc[j][1] - mn0); ps0 += sacc[j][1];
            sacc[j][2] = __expf(sacc[j][2] - mn1); ps1 += sacc[j][2];
            sacc[j][3] = __expf(sacc[j][3] - mn1); ps1 += sacc[j][3];
        }
        ps0 += __shfl_xor_sync(0xffffffffu, ps0, 1);
        ps0 += __shfl_xor_sync(0xffffffffu, ps0, 2);
        ps1 += __shfl_xor_sync(0xffffffffu, ps1, 1);
        ps1 += __shfl_xor_sync(0xffffffffu, ps1, 2);
        l0 = l0 * al0 + ps0;
        l1 = l1 * al1 + ps1;
        m0 = mn0; m1 = mn1;

#pragma unroll
        for (int jj = 0; jj < 16; jj++) {
            oacc[jj][0] *= al0; oacc[jj][1] *= al0;
            oacc[jj][2] *= al1; oacc[jj][3] *= al1;
        }

        // O += P @ V (3-term hi/lo; P repacked from S accumulators)
#pragma unroll
        for (int ks2 = 0; ks2 < 4; ks2++) {
            uint32_t ph[4], pl[4];
            ph[0] = pack_hilo(sacc[2 * ks2][0],     sacc[2 * ks2][1],     pl[0]);
            ph[1] = pack_hilo(sacc[2 * ks2][2],     sacc[2 * ks2][3],     pl[1]);
            ph[2] = pack_hilo(sacc[2 * ks2 + 1][0], sacc[2 * ks2 + 1][1], pl[2]);
            ph[3] = pack_hilo(sacc[2 * ks2 + 1][2], sacc[2 * ks2 + 1][3], pl[3]);
#pragma unroll
            for (int jj = 0; jj < 8; jj++) {
                uint32_t v4h[4], v4l[4];
                ldmx4(v4h, sVh + vfrag + (uint32_t)(jj * 16 * 144 + ks2 * 32));
                ldmx4(v4l, sVl + vfrag + (uint32_t)(jj * 16 * 144 + ks2 * 32));
                mma16816(oacc[2 * jj],     ph, &v4h[0]);
                mma16816(oacc[2 * jj],     ph, &v4l[0]);
                mma16816(oacc[2 * jj],     pl, &v4h[0]);
                mma16816(oacc[2 * jj + 1], ph, &v4h[2]);
                mma16816(oacc[2 * jj + 1], ph, &v4l[2]);
                mma16816(oacc[2 * jj + 1], pl, &v4h[2]);
            }
        }
        __syncthreads();
    }

    // epilogue: O/l -> bf16 hi/lo for the O GEMM
    float il0 = 1.0f / l0, il1 = 1.0f / l1;
    size_t row0 = qrow0 + wid * 16 + r;
    size_t base0 = row0 * 4096 + (size_t)h * 128 + colq;
    size_t base1 = (row0 + 8) * 4096 + (size_t)h * 128 + colq;
#pragma unroll
    for (int jj = 0; jj < 16; jj++) {
        uint32_t lo0, lo1;
        uint32_t hi0 = pack_hilo(oacc[jj][0] * il0, oacc[jj][1] * il0, lo0);
        uint32_t hi1 = pack_hilo(oacc[jj][2] * il1, oacc[jj][3] * il1, lo1);
        *(uint32_t*)(Ohi + base0 + jj * 8) = hi0;
        *(uint32_t*)(Olo + base0 + jj * 8) = lo0;
        *(uint32_t*)(Ohi + base1 + jj * 8) = hi1;
        *(uint32_t*)(Olo + base1 + jj * 8) = lo1;
    }
}

// ---------------------------------------------------------------------------
// Launcher
// ---------------------------------------------------------------------------
extern "C" void kernel_launch(void* const* d_in, const int* in_sizes, int n_in,
                              void* d_out, int out_size)
{
    (void)in_sizes; (void)n_in; (void)out_size;
    const int*   positions = (const int*)d_in[0];
    const float* hidden    = (const float*)d_in[1];
    const float* w_qkv     = (const float*)d_in[2];
    const float* w_o       = (const float*)d_in[3];
    const float* qw        = (const float*)d_in[4];
    const float* kw        = (const float*)d_in[5];
    float* out = (float*)d_out;

    float* qkv_ptr;
    __nv_bfloat16 *ahi, *alo, *bqhi, *bqlo, *wohi, *wolo;
    __nv_bfloat16 *khi, *klo, *vhi, *vlo, *ohi, *olo;
    cudaGetSymbolAddress((void**)&qkv_ptr, g_qkv);
    cudaGetSymbolAddress((void**)&ahi,  g_ahi);
    cudaGetSymbolAddress((void**)&alo,  g_alo);
    cudaGetSymbolAddress((void**)&bqhi, g_bqhi);
    cudaGetSymbolAddress((void**)&bqlo, g_bqlo);
    cudaGetSymbolAddress((void**)&wohi, g_wohi);
    cudaGetSymbolAddress((void**)&wolo, g_wolo);
    cudaGetSymbolAddress((void**)&khi,  g_khi);
    cudaGetSymbolAddress((void**)&klo,  g_klo);
    cudaGetSymbolAddress((void**)&vhi,  g_vhi);
    cudaGetSymbolAddress((void**)&vlo,  g_vlo);
    cudaGetSymbolAddress((void**)&ohi,  g_ohi);
    cudaGetSymbolAddress((void**)&olo,  g_olo);

    cudaFuncSetAttribute(gemm_mma_kernel,
        cudaFuncAttributeMaxDynamicSharedMemorySize, GEMM_SMEM);
    cudaFuncSetAttribute(attn_mma_kernel,
        cudaFuncAttributeMaxDynamicSharedMemorySize, ATT_SMEM);

    // 1) prep: split activations, split+transpose weights
    split_kernel<<<4096, 256>>>(hidden, ahi, alo, (size_t)MROWS * KDIM / 4);
    {
        dim3 g(QKVN / 32, KDIM / 32), bdim(32, 8);
        split_T_kernel<<<g, bdim>>>(w_qkv, bqhi, bqlo, KDIM, QKVN);
    }
    {
        dim3 g(DMODEL / 32, KDIM / 32), bdim(32, 8);
        split_T_kernel<<<g, bdim>>>(w_o, wohi, wolo, KDIM, DMODEL);
    }

    // 2) QKV GEMM (HMMA)
    {
        dim3 grid(QKVN / BN, MROWS / BM);
        gemm_mma_kernel<<<grid, 256, GEMM_SMEM>>>(ahi, alo, bqhi, bqlo,
                                                  qkv_ptr, QKVN);
    }

    // 3) RMSNorm + RoPE + pack to bf16 hi/lo (Q overwrites ahi/alo — dead by now)
    {
        int blocks = (MROWS * 48) / 8;   // 8 warps per 256-thread block
        normrope_pack_kernel<<<blocks, 256>>>(qkv_ptr, positions, qw, kw,
                                              ahi, alo, khi, klo, vhi, vlo);
    }

    // 4) causal GQA flash attention (HMMA, hi/lo)
    {
        dim3 grid(SEQ / 64, NH, BATCH);
        attn_mma_kernel<<<grid, 128, ATT_SMEM>>>(ahi, alo, khi, klo, vhi, vlo,
                                                 ohi, olo);
    }

    // 5) O GEMM (HMMA) straight from attention's bf16 hi/lo output
    {
        dim3 grid(DMODEL / BN, MROWS / BM);
        gemm_mma_kernel<<<grid, 256, GEMM_SMEM>>>(ohi, olo, wohi, wolo,
                                                  out, DMODEL);
    }
}